// round 9
// baseline (speedup 1.0000x reference)
#include <cuda_runtime.h>
#include <cuda_fp16.h>
#include <stdint.h>
#include <math.h>

#define N_NODES 200000
#define N_EDGES 500000
#define DIM 128
#define KQV_COLS 768   // bias layout: [k0 q0 v0 | k1 q1 v1]
#define NBUCK (2 * N_NODES)
#define SCAN_NB ((NBUCK + 2047) / 2048)   // 196

// ---------------- scratch (device globals; no allocation allowed) ----------------
__device__ __align__(16) float g_bc[KQV_COLS];                   // fused bias
__device__ __align__(16) __half g_WCt[KQV_COLS * 128];           // fused W^T [n][k], fp16
__device__ __align__(16) __half g_Wot[128 * 128];                // Wo^T [n][k], fp16
__device__ __align__(16) __half g_K[2 * (size_t)N_NODES * 128];  // fp16 K per rel
__device__ __align__(16) __half g_Q[2 * (size_t)N_NODES * 128];  // fp16 Q per rel (scaled)
__device__ __align__(16) __half g_V[2 * (size_t)N_NODES * 128];  // fp16 V per rel
__device__ __align__(16) __half g_upd[((size_t)N_NODES + 128) * DIM];  // summed update, fp16 (padded)
// CSR build
__device__ int g_cnt[NBUCK];
__device__ int g_head[NBUCK];
__device__ int g_off[NBUCK + 1];
__device__ int g_bsum[256];
__device__ int g_boff[256];
__device__ int g_esrc[2 * N_EDGES];

// ---------------- helpers ----------------
static __device__ __forceinline__ uint32_t smem_u32(const void* p) {
    uint32_t a;
    asm("{ .reg .u64 t; cvta.to.shared.u64 t, %1; cvt.u32.u64 %0, t; }" : "=r"(a) : "l"(p));
    return a;
}
static __device__ __forceinline__ uint32_t packh2(__half a, __half b) {
    uint16_t ua = *(uint16_t*)&a, ub = *(uint16_t*)&b;
    return (uint32_t)ua | ((uint32_t)ub << 16);
}

#define LDSM4(r, addr)                                                           \
    asm volatile("ldmatrix.sync.aligned.m8n8.x4.shared.b16 {%0,%1,%2,%3}, [%4];" \
                 : "=r"((r)[0]), "=r"((r)[1]), "=r"((r)[2]), "=r"((r)[3])        \
                 : "r"(addr))

#define MMAH(c, a, b0, b1)                                                    \
    asm volatile(                                                             \
        "mma.sync.aligned.m16n8k16.row.col.f32.f16.f16.f32 "                  \
        "{%0,%1,%2,%3},{%4,%5,%6,%7},{%8,%9},{%0,%1,%2,%3};"                  \
        : "+f"((c)[0]), "+f"((c)[1]), "+f"((c)[2]), "+f"((c)[3])              \
        : "r"((a)[0]), "r"((a)[1]), "r"((a)[2]), "r"((a)[3]), "r"(b0), "r"(b1))

#define CP_ASYNC16(dst, src) \
    asm volatile("cp.async.ca.shared.global [%0], [%1], 16;" :: "r"(dst), "l"(src))
#define CP_COMMIT() asm volatile("cp.async.commit_group;")
#define CP_WAIT0() asm volatile("cp.async.wait_group 0;")

// ---------------- CSR build ----------------
__global__ void zero_cnt_kernel() {
    int i = blockIdx.x * blockDim.x + threadIdx.x;
    if (i < NBUCK) g_cnt[i] = 0;
}

__global__ void hist_kernel(const int* __restrict__ dst0, const int* __restrict__ dst1) {
    int e = blockIdx.x * blockDim.x + threadIdx.x;
    if (e >= N_EDGES) return;
    int rel = blockIdx.y;
    const int* dst = rel ? dst1 : dst0;
    atomicAdd(&g_cnt[rel * N_NODES + dst[e]], 1);
}

// blocks of 2048 elements (256 thr x 8); per-block exclusive prefix + block sums
__global__ void scan1_kernel() {
    __shared__ int sh[256];
    int b = blockIdx.x, t = threadIdx.x;
    int base = b * 2048 + t * 8;
    int v[8];
    int sum = 0;
#pragma unroll
    for (int j = 0; j < 8; j++) {
        int idx = base + j;
        v[j] = (idx < NBUCK) ? g_cnt[idx] : 0;
        sum += v[j];
    }
    sh[t] = sum;
    __syncthreads();
    for (int off = 1; off < 256; off <<= 1) {
        int y = (t >= off) ? sh[t - off] : 0;
        __syncthreads();
        sh[t] += y;
        __syncthreads();
    }
    if (t == 255) g_bsum[b] = sh[255];
    int run = sh[t] - sum;   // exclusive within block
#pragma unroll
    for (int j = 0; j < 8; j++) {
        int idx = base + j;
        if (idx < NBUCK) g_off[idx] = run;
        run += v[j];
    }
}

__global__ void scan2_kernel() {
    __shared__ int sh[256];
    int t = threadIdx.x;
    int v = (t < SCAN_NB) ? g_bsum[t] : 0;
    sh[t] = v;
    __syncthreads();
    for (int off = 1; off < 256; off <<= 1) {
        int y = (t >= off) ? sh[t - off] : 0;
        __syncthreads();
        sh[t] += y;
        __syncthreads();
    }
    g_boff[t] = sh[t] - v;   // exclusive block offset
}

__global__ void scan3_kernel() {
    int b = blockIdx.x, t = threadIdx.x;
    int add = g_boff[b];
    int base = b * 2048 + t * 8;
#pragma unroll
    for (int j = 0; j < 8; j++) {
        int idx = base + j;
        if (idx < NBUCK) {
            int o = g_off[idx] + add;
            g_off[idx] = o;
            g_head[idx] = o;
        }
    }
    if (b == 0 && t == 0) g_off[NBUCK] = 2 * N_EDGES;
}

__global__ void scatter_kernel(const int* __restrict__ src0, const int* __restrict__ dst0,
                               const int* __restrict__ src1, const int* __restrict__ dst1) {
    int e = blockIdx.x * blockDim.x + threadIdx.x;
    if (e >= N_EDGES) return;
    int rel = blockIdx.y;
    const int* src = rel ? src1 : src0;
    const int* dst = rel ? dst1 : dst0;
    int pos = atomicAdd(&g_head[rel * N_NODES + dst[e]], 1);
    g_esrc[pos] = src[e];
}

// ---------------- fold node-type + edge-type linears; emit fp16 transposed ----------------
__global__ void prep_kernel(const float* __restrict__ Wk, const float* __restrict__ bk,
                            const float* __restrict__ Wq, const float* __restrict__ bq,
                            const float* __restrict__ Wv, const float* __restrict__ bv,
                            const float* __restrict__ We0, const float* __restrict__ be0,
                            const float* __restrict__ We1, const float* __restrict__ be1) {
    int c = blockIdx.x;           // 0..767
    int i = threadIdx.x;          // 0..127  (k index)
    int r = c / 384;
    int rem = c % 384;
    int t = rem / 128;
    int j = rem % 128;
    const float* We = r ? We1 : We0;
    const float* be = r ? be1 : be0;
    const float* Wt = (t == 0) ? Wk : (t == 1) ? Wq : Wv;
    const float* bt = (t == 0) ? bk : (t == 1) ? bq : bv;
    const float scale = (t == 1) ? 0.125f : 1.0f;

    __shared__ float sWe[128];
    sWe[i] = We[i * 128 + j];
    __syncthreads();

    float acc = 0.f;
#pragma unroll 8
    for (int m = 0; m < 128; m++) acc += Wt[i * 128 + m] * sWe[m];
    g_WCt[c * 128 + i] = __float2half_rn(acc * scale);

    if (i == 0) {
        float b = 0.f;
        for (int m = 0; m < 128; m++) b += bt[m] * sWe[m];
        g_bc[c] = (b + be[j]) * scale;
    }
}

__global__ void prep_wo_kernel(const float* __restrict__ Wo) {
    int n = blockIdx.x;   // 0..127
    int i = threadIdx.x;  // 0..127 (k index)
    g_Wot[n * 128 + i] = __float2half_rn(Wo[i * 128 + n]);
}

// ---------------- HMMA GEMM ----------------
// MODE 1: A fp32 -> fp16, C_kqv routed fp16 K/Q/V outputs (NTILES=6).
// MODE 0: A fp16 (g_upd) via cp.async; fp32 C + bias (NTILES=1).
// CTA: 256 threads, 128 rows, warp tile 32x64; smem 64KB (A 32K | B 32K); 2 CTAs/SM.
template <int MODE>
__global__ void __launch_bounds__(256, 2) hgemm_kernel(
    const void* __restrict__ Av,
    const __half* __restrict__ Bt,
    const float* __restrict__ bias,
    float* __restrict__ C,
    int COLS, int Mrows, int NTILES) {
    extern __shared__ char smem[];
    const uint32_t sb = smem_u32(smem);
    const int tid = threadIdx.x;
    const int m0 = blockIdx.x * 128;
    const int SM_BH = 32768;

    auto loadB = [&](int n0) {
#pragma unroll
        for (int it = 0; it < 8; it++) {
            int u = tid + it * 256;          // 0..2047
            int row = u >> 4, kb = u & 15;
            uint32_t off = row * 256 + ((uint32_t)(kb ^ (row & 7)) << 4);
            const char* gh = (const char*)(Bt + (size_t)(n0 + row) * 128) + kb * 16;
            CP_ASYNC16(sb + SM_BH + off, gh);
        }
    };
    loadB(0);

    // A tile: 128 rows x 128 cols fp16 (256B/row), swizzled
    if (MODE == 0) {
        const __half* Ah = (const __half*)Av;   // padded; no row guard needed
#pragma unroll
        for (int it = 0; it < 8; it++) {
            int u = tid + it * 256;
            int row = u >> 4, kb = u & 15;
            uint32_t off = row * 256 + ((uint32_t)(kb ^ (row & 7)) << 4);
            const char* ga = (const char*)(Ah + (size_t)(m0 + row) * 128) + kb * 16;
            CP_ASYNC16(sb + off, ga);
        }
        CP_COMMIT();
    } else {
        CP_COMMIT();
        const float* A = (const float*)Av;
#pragma unroll
        for (int it = 0; it < 8; it++) {
            int u = tid + it * 256;
            int row = u >> 4, kb = u & 15;
            int gr = m0 + row;
            float4 v0 = make_float4(0.f, 0.f, 0.f, 0.f), v1 = v0;
            if (gr < Mrows) {
                const float* p = A + (size_t)gr * 128 + kb * 8;
                v0 = *(const float4*)p;
                v1 = *(const float4*)(p + 4);
            }
            uint32_t off = row * 256 + ((uint32_t)(kb ^ (row & 7)) << 4);
            uint32_t h0 = packh2(__float2half_rn(v0.x), __float2half_rn(v0.y));
            uint32_t h1 = packh2(__float2half_rn(v0.z), __float2half_rn(v0.w));
            uint32_t h2 = packh2(__float2half_rn(v1.x), __float2half_rn(v1.y));
            uint32_t h3 = packh2(__float2half_rn(v1.z), __float2half_rn(v1.w));
            *(uint4*)(smem + off) = make_uint4(h0, h1, h2, h3);
        }
    }

    // 8 warps -> 4m x 2n grid of 32m x 64n warp tiles
    const int wid = tid >> 5, lane = tid & 31;
    const int wm = wid & 3, wn = wid >> 2;
    const uint32_t x7 = lane & 7;
    const uint32_t aRow = wm * 32 + (lane & 15);
    const uint32_t akoff = lane >> 4;
    const uint32_t bRow = wn * 64 + (lane & 7) + ((lane >> 4) << 3);
    const uint32_t bkoff = (lane >> 3) & 1;
    const uint32_t ah_base = sb + aRow * 256;
    const uint32_t bh_base = sb + SM_BH + bRow * 256;
    const int g = lane >> 2, tg = lane & 3;

    for (int nt = 0; nt < NTILES; nt++) {
        CP_WAIT0();
        __syncthreads();

        float acc[2][8][4] = {};
#pragma unroll
        for (int kc = 0; kc < 8; kc++) {
            const uint32_t kxa = (((2 * kc + akoff) ^ x7) << 4);
            const uint32_t kxb = (((2 * kc + bkoff) ^ x7) << 4);
            uint32_t AH[2][4], BH[4][4];
#pragma unroll
            for (int ma = 0; ma < 2; ma++) LDSM4(AH[ma], ah_base + ma * 4096 + kxa);
#pragma unroll
            for (int nb = 0; nb < 4; nb++) LDSM4(BH[nb], bh_base + nb * 4096 + kxb);
#pragma unroll
            for (int ma = 0; ma < 2; ma++)
#pragma unroll
                for (int nb = 0; nb < 4; nb++) {
                    MMAH(acc[ma][nb * 2 + 0], AH[ma], BH[nb][0], BH[nb][1]);
                    MMAH(acc[ma][nb * 2 + 1], AH[ma], BH[nb][2], BH[nb][3]);
                }
        }

        __syncthreads();
        if (nt + 1 < NTILES) {
            loadB((nt + 1) * 128);
            CP_COMMIT();
        }

        // ---- epilogue ----
        if (MODE == 0) {
#pragma unroll
            for (int ma = 0; ma < 2; ma++) {
                int row = m0 + wm * 32 + ma * 16 + g;
#pragma unroll
                for (int x = 0; x < 8; x++) {
                    int col = nt * 128 + wn * 64 + x * 8 + tg * 2;
                    float2 bb = *(const float2*)(bias + col);
                    float* c = acc[ma][x];
                    if (row < Mrows)
                        *(float2*)(C + (size_t)row * COLS + col) =
                            make_float2(c[0] + bb.x, c[1] + bb.y);
                    if (row + 8 < Mrows)
                        *(float2*)(C + (size_t)(row + 8) * COLS + col) =
                            make_float2(c[2] + bb.x, c[3] + bb.y);
                }
            }
        } else {
            int r = nt / 3, t = nt - r * 3;
            __half* hout = (t == 0 ? g_K : t == 1 ? g_Q : g_V) + (size_t)r * N_NODES * 128;
#pragma unroll
            for (int ma = 0; ma < 2; ma++) {
                int row = m0 + wm * 32 + ma * 16 + g;
#pragma unroll
                for (int x = 0; x < 8; x++) {
                    int j = wn * 64 + x * 8 + tg * 2;
                    float2 bb = *(const float2*)(bias + nt * 128 + j);
                    float* c = acc[ma][x];
                    if (row < Mrows)
                        *(__half2*)(hout + (size_t)row * 128 + j) =
                            __float22half2_rn(make_float2(c[0] + bb.x, c[1] + bb.y));
                    if (row + 8 < Mrows)
                        *(__half2*)(hout + (size_t)(row + 8) * 128 + j) =
                            __float22half2_rn(make_float2(c[2] + bb.x, c[3] + bb.y));
                }
            }
        }
    }
}

// ---------------- gather: warp per node, BOTH relations; writes fp16 summed update ----------------
__global__ void __launch_bounds__(256) gather_kernel() {
    int wid = threadIdx.x >> 5, lane = threadIdx.x & 31;
    int node = blockIdx.x * 8 + wid;
    if (node >= N_NODES) return;

    float4 total = make_float4(0.f, 0.f, 0.f, 0.f);
#pragma unroll
    for (int rel = 0; rel < 2; rel++) {
        int bucket = rel * N_NODES + node;
        int o0 = g_off[bucket], o1 = g_off[bucket + 1];
        if (o0 == o1) continue;
        const size_t rbase = (size_t)rel * N_NODES * 128;
        float2 qraw = ((const float2*)(g_Q + rbase + (size_t)node * 128))[lane];
        __half2 q0 = *reinterpret_cast<__half2*>(&qraw.x);
        __half2 q1 = *reinterpret_cast<__half2*>(&qraw.y);
        float2 fq0 = __half22float2(q0), fq1 = __half22float2(q1);

        float s = 0.f;
        float4 acc = make_float4(0.f, 0.f, 0.f, 0.f);
        for (int i = o0; i < o1; i++) {
            int sn = g_esrc[i];
            float2 kraw = ((const float2*)(g_K + rbase + (size_t)sn * 128))[lane];
            __half2 a0 = *reinterpret_cast<__half2*>(&kraw.x);
            __half2 a1 = *reinterpret_cast<__half2*>(&kraw.y);
            float2 fa0 = __half22float2(a0), fa1 = __half22float2(a1);
            float p = fa0.x * fq0.x + fa0.y * fq0.y + fa1.x * fq1.x + fa1.y * fq1.y;
            // reduce within 16-lane halves (head0: lanes 0-15, head1: 16-31)
            p += __shfl_xor_sync(0xffffffffu, p, 1);
            p += __shfl_xor_sync(0xffffffffu, p, 2);
            p += __shfl_xor_sync(0xffffffffu, p, 4);
            p += __shfl_xor_sync(0xffffffffu, p, 8);
            float el = expf(p);
            s += el;
            float2 vraw = ((const float2*)(g_V + rbase + (size_t)sn * 128))[lane];
            __half2 v0 = *reinterpret_cast<__half2*>(&vraw.x);
            __half2 v1 = *reinterpret_cast<__half2*>(&vraw.y);
            float2 f0 = __half22float2(v0), f1 = __half22float2(v1);
            acc.x += f0.x * el;
            acc.y += f0.y * el;
            acc.z += f1.x * el;
            acc.w += f1.y * el;
        }
        float inv = 1.f / s;
        total.x += acc.x * inv;
        total.y += acc.y * inv;
        total.z += acc.z * inv;
        total.w += acc.w * inv;
    }
    __half2 o0h = __float22half2_rn(make_float2(total.x, total.y));
    __half2 o1h = __float22half2_rn(make_float2(total.z, total.w));
    float2 packed;
    *reinterpret_cast<__half2*>(&packed.x) = o0h;
    *reinterpret_cast<__half2*>(&packed.y) = o1h;
    ((float2*)(g_upd + (size_t)node * 128))[lane] = packed;
}

// ---------------- launch ----------------
extern "C" void kernel_launch(void* const* d_in, const int* in_sizes, int n_in,
                              void* d_out, int out_size) {
    const float* feat = (const float*)d_in[0];
    const int* src0 = (const int*)d_in[1];
    const int* dst0 = (const int*)d_in[2];
    const int* src1 = (const int*)d_in[3];
    const int* dst1 = (const int*)d_in[4];
    const float* Wk = (const float*)d_in[5];
    const float* bk = (const float*)d_in[6];
    const float* Wq = (const float*)d_in[7];
    const float* bq = (const float*)d_in[8];
    const float* Wv = (const float*)d_in[9];
    const float* bv = (const float*)d_in[10];
    const float* Wo = (const float*)d_in[11];
    const float* bo = (const float*)d_in[12];
    const float* We0 = (const float*)d_in[13];
    const float* be0 = (const float*)d_in[14];
    const float* We1 = (const float*)d_in[15];
    const float* be1 = (const float*)d_in[16];
    float* out = (float*)d_out;

    void *pbc, *pWC, *pWo, *pUpd;
    cudaGetSymbolAddress(&pbc, g_bc);
    cudaGetSymbolAddress(&pWC, g_WCt);
    cudaGetSymbolAddress(&pWo, g_Wot);
    cudaGetSymbolAddress(&pUpd, g_upd);

    cudaFuncSetAttribute(hgemm_kernel<1>, cudaFuncAttributeMaxDynamicSharedMemorySize, 65536);
    cudaFuncSetAttribute(hgemm_kernel<0>, cudaFuncAttributeMaxDynamicSharedMemorySize, 65536);

    // CSR build
    zero_cnt_kernel<<<(NBUCK + 255) / 256, 256>>>();
    hist_kernel<<<dim3((N_EDGES + 255) / 256, 2), 256>>>(dst0, dst1);
    scan1_kernel<<<SCAN_NB, 256>>>();
    scan2_kernel<<<1, 256>>>();
    scan3_kernel<<<SCAN_NB, 256>>>();
    scatter_kernel<<<dim3((N_EDGES + 255) / 256, 2), 256>>>(src0, dst0, src1, dst1);

    // weights
    prep_kernel<<<KQV_COLS, 128>>>(Wk, bk, Wq, bq, Wv, bv, We0, be0, We1, be1);
    prep_wo_kernel<<<128, 128>>>(Wo);

    const int Mtiles = (N_NODES + 127) / 128;  // 1563

    // K/Q/V = feat @ WC + bc   (single-pass fp16)
    hgemm_kernel<1><<<Mtiles, 256, 65536>>>(
        feat, (const __half*)pWC, (const float*)pbc, nullptr, KQV_COLS, N_NODES, 6);

    // per-destination softmax + message aggregation over both relations -> fp16 upd
    gather_kernel<<<(N_NODES + 7) / 8, 256>>>();

    // out = upd @ Wo + bo   (fp16 single-pass, A via cp.async)
    hgemm_kernel<0><<<Mtiles, 256, 65536>>>(
        pUpd, (const __half*)pWo, bo, out, DIM, N_NODES, 1);
}

// round 10
// speedup vs baseline: 1.0011x; 1.0011x over previous
#include <cuda_runtime.h>
#include <cuda_fp16.h>
#include <stdint.h>
#include <math.h>

#define N_NODES 200000
#define N_EDGES 500000
#define DIM 128
#define KQV_COLS 768   // bias layout: [k0 q0 v0 | k1 q1 v1]
#define NBUCK (2 * N_NODES)
#define SCAN_NB ((NBUCK + 2047) / 2048)   // 196

// ---------------- scratch (device globals; no allocation allowed) ----------------
__device__ __align__(16) float g_bc[KQV_COLS];                   // fused bias
__device__ __align__(16) __half g_WCt[KQV_COLS * 128];           // fused W^T [n][k], fp16
__device__ __align__(16) __half g_Wot[128 * 128];                // Wo^T [n][k], fp16
__device__ __align__(16) __half g_K[2 * (size_t)N_NODES * 128];  // fp16 K per rel
__device__ __align__(16) __half g_Q[2 * (size_t)N_NODES * 128];  // fp16 Q per rel (scaled)
__device__ __align__(16) __half g_V[2 * (size_t)N_NODES * 128];  // fp16 V per rel
__device__ __align__(16) __half g_upd[((size_t)N_NODES + 128) * DIM];  // summed update, fp16 (padded)
// CSR build
__device__ int g_cnt[NBUCK];
__device__ int g_head[NBUCK];
__device__ int g_off[NBUCK + 1];
__device__ int g_bsum[256];
__device__ int g_boff[256];
__device__ int g_esrc[2 * N_EDGES];

// ---------------- helpers ----------------
static __device__ __forceinline__ uint32_t smem_u32(const void* p) {
    uint32_t a;
    asm("{ .reg .u64 t; cvta.to.shared.u64 t, %1; cvt.u32.u64 %0, t; }" : "=r"(a) : "l"(p));
    return a;
}
static __device__ __forceinline__ uint32_t packh2(__half a, __half b) {
    uint16_t ua = *(uint16_t*)&a, ub = *(uint16_t*)&b;
    return (uint32_t)ua | ((uint32_t)ub << 16);
}

#define LDSM4(r, addr)                                                           \
    asm volatile("ldmatrix.sync.aligned.m8n8.x4.shared.b16 {%0,%1,%2,%3}, [%4];" \
                 : "=r"((r)[0]), "=r"((r)[1]), "=r"((r)[2]), "=r"((r)[3])        \
                 : "r"(addr))

#define MMAH(c, a, b0, b1)                                                    \
    asm volatile(                                                             \
        "mma.sync.aligned.m16n8k16.row.col.f32.f16.f16.f32 "                  \
        "{%0,%1,%2,%3},{%4,%5,%6,%7},{%8,%9},{%0,%1,%2,%3};"                  \
        : "+f"((c)[0]), "+f"((c)[1]), "+f"((c)[2]), "+f"((c)[3])              \
        : "r"((a)[0]), "r"((a)[1]), "r"((a)[2]), "r"((a)[3]), "r"(b0), "r"(b1))

#define CP_ASYNC16(dst, src) \
    asm volatile("cp.async.ca.shared.global [%0], [%1], 16;" :: "r"(dst), "l"(src))
#define CP_COMMIT() asm volatile("cp.async.commit_group;")
#define CP_WAIT0() asm volatile("cp.async.wait_group 0;")

// ---------------- CSR build ----------------
__global__ void zero_cnt_kernel() {
    int i = blockIdx.x * blockDim.x + threadIdx.x;
    if (i < NBUCK) g_cnt[i] = 0;
}

__global__ void hist_kernel(const int* __restrict__ dst0, const int* __restrict__ dst1) {
    int e = blockIdx.x * blockDim.x + threadIdx.x;
    if (e >= N_EDGES) return;
    int rel = blockIdx.y;
    const int* dst = rel ? dst1 : dst0;
    atomicAdd(&g_cnt[rel * N_NODES + dst[e]], 1);
}

// blocks of 2048 elements (256 thr x 8); per-block exclusive prefix + block sums
__global__ void scan1_kernel() {
    __shared__ int sh[256];
    int b = blockIdx.x, t = threadIdx.x;
    int base = b * 2048 + t * 8;
    int v[8];
    int sum = 0;
#pragma unroll
    for (int j = 0; j < 8; j++) {
        int idx = base + j;
        v[j] = (idx < NBUCK) ? g_cnt[idx] : 0;
        sum += v[j];
    }
    sh[t] = sum;
    __syncthreads();
    for (int off = 1; off < 256; off <<= 1) {
        int y = (t >= off) ? sh[t - off] : 0;
        __syncthreads();
        sh[t] += y;
        __syncthreads();
    }
    if (t == 255) g_bsum[b] = sh[255];
    int run = sh[t] - sum;   // exclusive within block
#pragma unroll
    for (int j = 0; j < 8; j++) {
        int idx = base + j;
        if (idx < NBUCK) g_off[idx] = run;
        run += v[j];
    }
}

__global__ void scan2_kernel() {
    __shared__ int sh[256];
    int t = threadIdx.x;
    int v = (t < SCAN_NB) ? g_bsum[t] : 0;
    sh[t] = v;
    __syncthreads();
    for (int off = 1; off < 256; off <<= 1) {
        int y = (t >= off) ? sh[t - off] : 0;
        __syncthreads();
        sh[t] += y;
        __syncthreads();
    }
    g_boff[t] = sh[t] - v;   // exclusive block offset
}

__global__ void scan3_kernel() {
    int b = blockIdx.x, t = threadIdx.x;
    int add = g_boff[b];
    int base = b * 2048 + t * 8;
#pragma unroll
    for (int j = 0; j < 8; j++) {
        int idx = base + j;
        if (idx < NBUCK) {
            int o = g_off[idx] + add;
            g_off[idx] = o;
            g_head[idx] = o;
        }
    }
    if (b == 0 && t == 0) g_off[NBUCK] = 2 * N_EDGES;
}

__global__ void scatter_kernel(const int* __restrict__ src0, const int* __restrict__ dst0,
                               const int* __restrict__ src1, const int* __restrict__ dst1) {
    int e = blockIdx.x * blockDim.x + threadIdx.x;
    if (e >= N_EDGES) return;
    int rel = blockIdx.y;
    const int* src = rel ? src1 : src0;
    const int* dst = rel ? dst1 : dst0;
    int pos = atomicAdd(&g_head[rel * N_NODES + dst[e]], 1);
    g_esrc[pos] = src[e];
}

// ---------------- fold node-type + edge-type linears; emit fp16 transposed ----------------
__global__ void prep_kernel(const float* __restrict__ Wk, const float* __restrict__ bk,
                            const float* __restrict__ Wq, const float* __restrict__ bq,
                            const float* __restrict__ Wv, const float* __restrict__ bv,
                            const float* __restrict__ We0, const float* __restrict__ be0,
                            const float* __restrict__ We1, const float* __restrict__ be1) {
    int c = blockIdx.x;           // 0..767
    int i = threadIdx.x;          // 0..127  (k index)
    int r = c / 384;
    int rem = c % 384;
    int t = rem / 128;
    int j = rem % 128;
    const float* We = r ? We1 : We0;
    const float* be = r ? be1 : be0;
    const float* Wt = (t == 0) ? Wk : (t == 1) ? Wq : Wv;
    const float* bt = (t == 0) ? bk : (t == 1) ? bq : bv;
    const float scale = (t == 1) ? 0.125f : 1.0f;

    __shared__ float sWe[128];
    sWe[i] = We[i * 128 + j];
    __syncthreads();

    float acc = 0.f;
#pragma unroll 8
    for (int m = 0; m < 128; m++) acc += Wt[i * 128 + m] * sWe[m];
    g_WCt[c * 128 + i] = __float2half_rn(acc * scale);

    if (i == 0) {
        float b = 0.f;
        for (int m = 0; m < 128; m++) b += bt[m] * sWe[m];
        g_bc[c] = (b + be[j]) * scale;
    }
}

__global__ void prep_wo_kernel(const float* __restrict__ Wo) {
    int n = blockIdx.x;   // 0..127
    int i = threadIdx.x;  // 0..127 (k index)
    g_Wot[n * 128 + i] = __float2half_rn(Wo[i * 128 + n]);
}

// ---------------- HMMA GEMM ----------------
// MODE 1: A fp32 -> fp16, C_kqv routed fp16 K/Q/V outputs (NTILES=6).
// MODE 0: A fp16 (g_upd) via cp.async; fp32 C + bias (NTILES=1).
// CTA: 256 threads, 128 rows, warp tile 32x64; smem 64KB (A 32K | B 32K); 2 CTAs/SM.
template <int MODE>
__global__ void __launch_bounds__(256, 2) hgemm_kernel(
    const void* __restrict__ Av,
    const __half* __restrict__ Bt,
    const float* __restrict__ bias,
    float* __restrict__ C,
    int COLS, int Mrows, int NTILES) {
    extern __shared__ char smem[];
    const uint32_t sb = smem_u32(smem);
    const int tid = threadIdx.x;
    const int m0 = blockIdx.x * 128;
    const int SM_BH = 32768;

    auto loadB = [&](int n0) {
#pragma unroll
        for (int it = 0; it < 8; it++) {
            int u = tid + it * 256;          // 0..2047
            int row = u >> 4, kb = u & 15;
            uint32_t off = row * 256 + ((uint32_t)(kb ^ (row & 7)) << 4);
            const char* gh = (const char*)(Bt + (size_t)(n0 + row) * 128) + kb * 16;
            CP_ASYNC16(sb + SM_BH + off, gh);
        }
    };
    loadB(0);

    // A tile: 128 rows x 128 cols fp16 (256B/row), swizzled
    if (MODE == 0) {
        const __half* Ah = (const __half*)Av;   // padded; no row guard needed
#pragma unroll
        for (int it = 0; it < 8; it++) {
            int u = tid + it * 256;
            int row = u >> 4, kb = u & 15;
            uint32_t off = row * 256 + ((uint32_t)(kb ^ (row & 7)) << 4);
            const char* ga = (const char*)(Ah + (size_t)(m0 + row) * 128) + kb * 16;
            CP_ASYNC16(sb + off, ga);
        }
        CP_COMMIT();
    } else {
        CP_COMMIT();
        const float* A = (const float*)Av;
#pragma unroll
        for (int it = 0; it < 8; it++) {
            int u = tid + it * 256;
            int row = u >> 4, kb = u & 15;
            int gr = m0 + row;
            float4 v0 = make_float4(0.f, 0.f, 0.f, 0.f), v1 = v0;
            if (gr < Mrows) {
                const float* p = A + (size_t)gr * 128 + kb * 8;
                v0 = *(const float4*)p;
                v1 = *(const float4*)(p + 4);
            }
            uint32_t off = row * 256 + ((uint32_t)(kb ^ (row & 7)) << 4);
            uint32_t h0 = packh2(__float2half_rn(v0.x), __float2half_rn(v0.y));
            uint32_t h1 = packh2(__float2half_rn(v0.z), __float2half_rn(v0.w));
            uint32_t h2 = packh2(__float2half_rn(v1.x), __float2half_rn(v1.y));
            uint32_t h3 = packh2(__float2half_rn(v1.z), __float2half_rn(v1.w));
            *(uint4*)(smem + off) = make_uint4(h0, h1, h2, h3);
        }
    }

    // 8 warps -> 4m x 2n grid of 32m x 64n warp tiles
    const int wid = tid >> 5, lane = tid & 31;
    const int wm = wid & 3, wn = wid >> 2;
    const uint32_t x7 = lane & 7;
    const uint32_t aRow = wm * 32 + (lane & 15);
    const uint32_t akoff = lane >> 4;
    const uint32_t bRow = wn * 64 + (lane & 7) + ((lane >> 4) << 3);
    const uint32_t bkoff = (lane >> 3) & 1;
    const uint32_t ah_base = sb + aRow * 256;
    const uint32_t bh_base = sb + SM_BH + bRow * 256;
    const int g = lane >> 2, tg = lane & 3;

    for (int nt = 0; nt < NTILES; nt++) {
        CP_WAIT0();
        __syncthreads();

        float acc[2][8][4] = {};
#pragma unroll
        for (int kc = 0; kc < 8; kc++) {
            const uint32_t kxa = (((2 * kc + akoff) ^ x7) << 4);
            const uint32_t kxb = (((2 * kc + bkoff) ^ x7) << 4);
            uint32_t AH[2][4], BH[4][4];
#pragma unroll
            for (int ma = 0; ma < 2; ma++) LDSM4(AH[ma], ah_base + ma * 4096 + kxa);
#pragma unroll
            for (int nb = 0; nb < 4; nb++) LDSM4(BH[nb], bh_base + nb * 4096 + kxb);
#pragma unroll
            for (int ma = 0; ma < 2; ma++)
#pragma unroll
                for (int nb = 0; nb < 4; nb++) {
                    MMAH(acc[ma][nb * 2 + 0], AH[ma], BH[nb][0], BH[nb][1]);
                    MMAH(acc[ma][nb * 2 + 1], AH[ma], BH[nb][2], BH[nb][3]);
                }
        }

        __syncthreads();
        if (nt + 1 < NTILES) {
            loadB((nt + 1) * 128);
            CP_COMMIT();
        }

        // ---- epilogue ----
        if (MODE == 0) {
#pragma unroll
            for (int ma = 0; ma < 2; ma++) {
                int row = m0 + wm * 32 + ma * 16 + g;
#pragma unroll
                for (int x = 0; x < 8; x++) {
                    int col = nt * 128 + wn * 64 + x * 8 + tg * 2;
                    float2 bb = *(const float2*)(bias + col);
                    float* c = acc[ma][x];
                    if (row < Mrows)
                        *(float2*)(C + (size_t)row * COLS + col) =
                            make_float2(c[0] + bb.x, c[1] + bb.y);
                    if (row + 8 < Mrows)
                        *(float2*)(C + (size_t)(row + 8) * COLS + col) =
                            make_float2(c[2] + bb.x, c[3] + bb.y);
                }
            }
        } else {
            int r = nt / 3, t = nt - r * 3;
            __half* hout = (t == 0 ? g_K : t == 1 ? g_Q : g_V) + (size_t)r * N_NODES * 128;
#pragma unroll
            for (int ma = 0; ma < 2; ma++) {
                int row = m0 + wm * 32 + ma * 16 + g;
#pragma unroll
                for (int x = 0; x < 8; x++) {
                    int j = wn * 64 + x * 8 + tg * 2;
                    float2 bb = *(const float2*)(bias + nt * 128 + j);
                    float* c = acc[ma][x];
                    if (row < Mrows)
                        *(__half2*)(hout + (size_t)row * 128 + j) =
                            __float22half2_rn(make_float2(c[0] + bb.x, c[1] + bb.y));
                    if (row + 8 < Mrows)
                        *(__half2*)(hout + (size_t)(row + 8) * 128 + j) =
                            __float22half2_rn(make_float2(c[2] + bb.x, c[3] + bb.y));
                }
            }
        }
    }
}

// ---------------- gather: 2 warps per node (one per rel), smem combine, fp16 write ----------------
__global__ void __launch_bounds__(256) gather_kernel() {
    __shared__ float4 s_part[4][32];
    int wid = threadIdx.x >> 5, lane = threadIdx.x & 31;
    int slot = wid >> 1;             // 0..3: node slot within block
    int rel = wid & 1;
    int node = blockIdx.x * 4 + slot;

    float4 part = make_float4(0.f, 0.f, 0.f, 0.f);
    if (node < N_NODES) {
        int bucket = rel * N_NODES + node;
        int o0 = g_off[bucket], o1 = g_off[bucket + 1];
        if (o0 < o1) {
            const size_t rbase = (size_t)rel * N_NODES * 128;
            float2 qraw = ((const float2*)(g_Q + rbase + (size_t)node * 128))[lane];
            __half2 q0 = *reinterpret_cast<__half2*>(&qraw.x);
            __half2 q1 = *reinterpret_cast<__half2*>(&qraw.y);
            float2 fq0 = __half22float2(q0), fq1 = __half22float2(q1);

            float s = 0.f;
            float4 acc = make_float4(0.f, 0.f, 0.f, 0.f);
            for (int c = o0; c < o1; c += 32) {
                int cnt = min(32, o1 - c);
                // coalesced index load; broadcast via shfl (removes dependent index chain)
                int myidx = (lane < cnt) ? g_esrc[c + lane] : 0;
                for (int j = 0; j < cnt; j++) {
                    int sn = __shfl_sync(0xffffffffu, myidx, j);
                    float2 kraw = ((const float2*)(g_K + rbase + (size_t)sn * 128))[lane];
                    __half2 a0 = *reinterpret_cast<__half2*>(&kraw.x);
                    __half2 a1 = *reinterpret_cast<__half2*>(&kraw.y);
                    float2 fa0 = __half22float2(a0), fa1 = __half22float2(a1);
                    float p = fa0.x * fq0.x + fa0.y * fq0.y + fa1.x * fq1.x + fa1.y * fq1.y;
                    // reduce within 16-lane halves (head0: lanes 0-15, head1: 16-31)
                    p += __shfl_xor_sync(0xffffffffu, p, 1);
                    p += __shfl_xor_sync(0xffffffffu, p, 2);
                    p += __shfl_xor_sync(0xffffffffu, p, 4);
                    p += __shfl_xor_sync(0xffffffffu, p, 8);
                    float el = __expf(p);
                    s += el;
                    float2 vraw = ((const float2*)(g_V + rbase + (size_t)sn * 128))[lane];
                    __half2 v0 = *reinterpret_cast<__half2*>(&vraw.x);
                    __half2 v1 = *reinterpret_cast<__half2*>(&vraw.y);
                    float2 f0 = __half22float2(v0), f1 = __half22float2(v1);
                    acc.x += f0.x * el;
                    acc.y += f0.y * el;
                    acc.z += f1.x * el;
                    acc.w += f1.y * el;
                }
            }
            float inv = 1.f / s;
            part = make_float4(acc.x * inv, acc.y * inv, acc.z * inv, acc.w * inv);
        }
    }
    if (rel == 1) s_part[slot][lane] = part;
    __syncthreads();
    if (rel == 0 && node < N_NODES) {
        float4 o = s_part[slot][lane];
        float4 total = make_float4(part.x + o.x, part.y + o.y, part.z + o.z, part.w + o.w);
        __half2 h0 = __float22half2_rn(make_float2(total.x, total.y));
        __half2 h1 = __float22half2_rn(make_float2(total.z, total.w));
        float2 packed;
        *reinterpret_cast<__half2*>(&packed.x) = h0;
        *reinterpret_cast<__half2*>(&packed.y) = h1;
        ((float2*)(g_upd + (size_t)node * 128))[lane] = packed;
    }
}

// ---------------- launch ----------------
extern "C" void kernel_launch(void* const* d_in, const int* in_sizes, int n_in,
                              void* d_out, int out_size) {
    const float* feat = (const float*)d_in[0];
    const int* src0 = (const int*)d_in[1];
    const int* dst0 = (const int*)d_in[2];
    const int* src1 = (const int*)d_in[3];
    const int* dst1 = (const int*)d_in[4];
    const float* Wk = (const float*)d_in[5];
    const float* bk = (const float*)d_in[6];
    const float* Wq = (const float*)d_in[7];
    const float* bq = (const float*)d_in[8];
    const float* Wv = (const float*)d_in[9];
    const float* bv = (const float*)d_in[10];
    const float* Wo = (const float*)d_in[11];
    const float* bo = (const float*)d_in[12];
    const float* We0 = (const float*)d_in[13];
    const float* be0 = (const float*)d_in[14];
    const float* We1 = (const float*)d_in[15];
    const float* be1 = (const float*)d_in[16];
    float* out = (float*)d_out;

    void *pbc, *pWC, *pWo, *pUpd;
    cudaGetSymbolAddress(&pbc, g_bc);
    cudaGetSymbolAddress(&pWC, g_WCt);
    cudaGetSymbolAddress(&pWo, g_Wot);
    cudaGetSymbolAddress(&pUpd, g_upd);

    cudaFuncSetAttribute(hgemm_kernel<1>, cudaFuncAttributeMaxDynamicSharedMemorySize, 65536);
    cudaFuncSetAttribute(hgemm_kernel<0>, cudaFuncAttributeMaxDynamicSharedMemorySize, 65536);

    // CSR build
    zero_cnt_kernel<<<(NBUCK + 255) / 256, 256>>>();
    hist_kernel<<<dim3((N_EDGES + 255) / 256, 2), 256>>>(dst0, dst1);
    scan1_kernel<<<SCAN_NB, 256>>>();
    scan2_kernel<<<1, 256>>>();
    scan3_kernel<<<SCAN_NB, 256>>>();
    scatter_kernel<<<dim3((N_EDGES + 255) / 256, 2), 256>>>(src0, dst0, src1, dst1);

    // weights
    prep_kernel<<<KQV_COLS, 128>>>(Wk, bk, Wq, bq, Wv, bv, We0, be0, We1, be1);
    prep_wo_kernel<<<128, 128>>>(Wo);

    const int Mtiles = (N_NODES + 127) / 128;  // 1563

    // K/Q/V = feat @ WC + bc   (single-pass fp16)
    hgemm_kernel<1><<<Mtiles, 256, 65536>>>(
        feat, (const __half*)pWC, (const float*)pbc, nullptr, KQV_COLS, N_NODES, 6);

    // per-destination softmax + message aggregation (2 warps/node) -> fp16 upd
    gather_kernel<<<(N_NODES + 3) / 4, 256>>>();

    // out = upd @ Wo + bo   (fp16 single-pass, A via cp.async)
    hgemm_kernel<0><<<Mtiles, 256, 65536>>>(
        pUpd, (const __half*)pWo, bo, out, DIM, N_NODES, 1);
}

// round 11
// speedup vs baseline: 1.1188x; 1.1176x over previous
#include <cuda_runtime.h>
#include <cuda_fp16.h>
#include <stdint.h>
#include <math.h>

#define N_NODES 200000
#define N_EDGES 500000
#define DIM 128
#define KQV_COLS 768   // bias layout: [k0 q0 v0 | k1 q1 v1]
#define NBUCK (2 * N_NODES)
#define SCAN_NB ((NBUCK + 2047) / 2048)   // 196

// ---------------- scratch (device globals; no allocation allowed) ----------------
__device__ __align__(16) float g_bc[KQV_COLS];                   // fused bias
__device__ __align__(16) __half g_WCt[KQV_COLS * 128];           // fused W^T [n][k], fp16
__device__ __align__(16) __half g_Wot[128 * 128];                // Wo^T [n][k], fp16
__device__ __align__(16) __half g_K[2 * (size_t)N_NODES * 128];  // fp16 K per rel
__device__ __align__(16) __half g_Q[2 * (size_t)N_NODES * 128];  // fp16 Q per rel (scaled)
__device__ __align__(16) __half g_V[2 * (size_t)N_NODES * 128];  // fp16 V per rel
__device__ __align__(16) __half g_updh0[((size_t)N_NODES + 128) * DIM];  // rel0 normalized, fp16 (padded)
__device__ __align__(16) __half g_updh1[((size_t)N_NODES + 128) * DIM];  // rel1 normalized, fp16 (padded)
// CSR build
__device__ int g_cnt[NBUCK];
__device__ int g_head[NBUCK];
__device__ int g_off[NBUCK + 1];
__device__ int g_bsum[256];
__device__ int g_boff[256];
__device__ int g_esrc[2 * N_EDGES];

// ---------------- helpers ----------------
static __device__ __forceinline__ uint32_t smem_u32(const void* p) {
    uint32_t a;
    asm("{ .reg .u64 t; cvta.to.shared.u64 t, %1; cvt.u32.u64 %0, t; }" : "=r"(a) : "l"(p));
    return a;
}
static __device__ __forceinline__ uint32_t packh2(__half a, __half b) {
    uint16_t ua = *(uint16_t*)&a, ub = *(uint16_t*)&b;
    return (uint32_t)ua | ((uint32_t)ub << 16);
}
// add two packed half2 pairs in fp32 and repack
static __device__ __forceinline__ uint32_t addh2(uint32_t a, uint32_t b) {
    __half2 ha = *reinterpret_cast<__half2*>(&a);
    __half2 hb = *reinterpret_cast<__half2*>(&b);
    float2 fa = __half22float2(ha), fb = __half22float2(hb);
    __half2 r = __float22half2_rn(make_float2(fa.x + fb.x, fa.y + fb.y));
    return *reinterpret_cast<uint32_t*>(&r);
}

#define LDSM4(r, addr)                                                           \
    asm volatile("ldmatrix.sync.aligned.m8n8.x4.shared.b16 {%0,%1,%2,%3}, [%4];" \
                 : "=r"((r)[0]), "=r"((r)[1]), "=r"((r)[2]), "=r"((r)[3])        \
                 : "r"(addr))

#define MMAH(c, a, b0, b1)                                                    \
    asm volatile(                                                             \
        "mma.sync.aligned.m16n8k16.row.col.f32.f16.f16.f32 "                  \
        "{%0,%1,%2,%3},{%4,%5,%6,%7},{%8,%9},{%0,%1,%2,%3};"                  \
        : "+f"((c)[0]), "+f"((c)[1]), "+f"((c)[2]), "+f"((c)[3])              \
        : "r"((a)[0]), "r"((a)[1]), "r"((a)[2]), "r"((a)[3]), "r"(b0), "r"(b1))

#define CP_ASYNC16(dst, src) \
    asm volatile("cp.async.ca.shared.global [%0], [%1], 16;" :: "r"(dst), "l"(src))
#define CP_COMMIT() asm volatile("cp.async.commit_group;")
#define CP_WAIT(n) asm volatile("cp.async.wait_group %0;" :: "n"(n))

// ---------------- CSR build ----------------
__global__ void zero_cnt_kernel() {
    int i = blockIdx.x * blockDim.x + threadIdx.x;
    if (i < NBUCK) g_cnt[i] = 0;
}

__global__ void hist_kernel(const int* __restrict__ dst0, const int* __restrict__ dst1) {
    int e = blockIdx.x * blockDim.x + threadIdx.x;
    if (e >= N_EDGES) return;
    int rel = blockIdx.y;
    const int* dst = rel ? dst1 : dst0;
    atomicAdd(&g_cnt[rel * N_NODES + dst[e]], 1);
}

// blocks of 2048 elements (256 thr x 8); per-block exclusive prefix + block sums
__global__ void scan1_kernel() {
    __shared__ int sh[256];
    int b = blockIdx.x, t = threadIdx.x;
    int base = b * 2048 + t * 8;
    int v[8];
    int sum = 0;
#pragma unroll
    for (int j = 0; j < 8; j++) {
        int idx = base + j;
        v[j] = (idx < NBUCK) ? g_cnt[idx] : 0;
        sum += v[j];
    }
    sh[t] = sum;
    __syncthreads();
    for (int off = 1; off < 256; off <<= 1) {
        int y = (t >= off) ? sh[t - off] : 0;
        __syncthreads();
        sh[t] += y;
        __syncthreads();
    }
    if (t == 255) g_bsum[b] = sh[255];
    int run = sh[t] - sum;   // exclusive within block
#pragma unroll
    for (int j = 0; j < 8; j++) {
        int idx = base + j;
        if (idx < NBUCK) g_off[idx] = run;
        run += v[j];
    }
}

__global__ void scan2_kernel() {
    __shared__ int sh[256];
    int t = threadIdx.x;
    int v = (t < SCAN_NB) ? g_bsum[t] : 0;
    sh[t] = v;
    __syncthreads();
    for (int off = 1; off < 256; off <<= 1) {
        int y = (t >= off) ? sh[t - off] : 0;
        __syncthreads();
        sh[t] += y;
        __syncthreads();
    }
    g_boff[t] = sh[t] - v;   // exclusive block offset
}

__global__ void scan3_kernel() {
    int b = blockIdx.x, t = threadIdx.x;
    int add = g_boff[b];
    int base = b * 2048 + t * 8;
#pragma unroll
    for (int j = 0; j < 8; j++) {
        int idx = base + j;
        if (idx < NBUCK) {
            int o = g_off[idx] + add;
            g_off[idx] = o;
            g_head[idx] = o;
        }
    }
    if (b == 0 && t == 0) g_off[NBUCK] = 2 * N_EDGES;
}

__global__ void scatter_kernel(const int* __restrict__ src0, const int* __restrict__ dst0,
                               const int* __restrict__ src1, const int* __restrict__ dst1) {
    int e = blockIdx.x * blockDim.x + threadIdx.x;
    if (e >= N_EDGES) return;
    int rel = blockIdx.y;
    const int* src = rel ? src1 : src0;
    const int* dst = rel ? dst1 : dst0;
    int pos = atomicAdd(&g_head[rel * N_NODES + dst[e]], 1);
    g_esrc[pos] = src[e];
}

// ---------------- fold node-type + edge-type linears; emit fp16 transposed ----------------
__global__ void prep_kernel(const float* __restrict__ Wk, const float* __restrict__ bk,
                            const float* __restrict__ Wq, const float* __restrict__ bq,
                            const float* __restrict__ Wv, const float* __restrict__ bv,
                            const float* __restrict__ We0, const float* __restrict__ be0,
                            const float* __restrict__ We1, const float* __restrict__ be1) {
    int c = blockIdx.x;           // 0..767
    int i = threadIdx.x;          // 0..127  (k index)
    int r = c / 384;
    int rem = c % 384;
    int t = rem / 128;
    int j = rem % 128;
    const float* We = r ? We1 : We0;
    const float* be = r ? be1 : be0;
    const float* Wt = (t == 0) ? Wk : (t == 1) ? Wq : Wv;
    const float* bt = (t == 0) ? bk : (t == 1) ? bq : bv;
    const float scale = (t == 1) ? 0.125f : 1.0f;

    __shared__ float sWe[128];
    sWe[i] = We[i * 128 + j];
    __syncthreads();

    float acc = 0.f;
#pragma unroll 8
    for (int m = 0; m < 128; m++) acc += Wt[i * 128 + m] * sWe[m];
    g_WCt[c * 128 + i] = __float2half_rn(acc * scale);

    if (i == 0) {
        float b = 0.f;
        for (int m = 0; m < 128; m++) b += bt[m] * sWe[m];
        g_bc[c] = (b + be[j]) * scale;
    }
}

__global__ void prep_wo_kernel(const float* __restrict__ Wo) {
    int n = blockIdx.x;   // 0..127
    int i = threadIdx.x;  // 0..127 (k index)
    g_Wot[n * 128 + i] = __float2half_rn(Wo[i * 128 + n]);
}

// ---------------- HMMA GEMM ----------------
// MODE 1: A = fp32 feat -> fp16; C routed fp16 K/Q/V outputs (NTILES=6).
// MODE 0: A = fp16 (g_updh0 + g_updh1); fp32 C + bias (NTILES=1).
// CTA: 256 threads, 128 rows, warp tile 32x64; smem 96KB (A 32K | B0 32K | B1 32K); 2 CTAs/SM.
// B double-buffered: B(nt+1) load overlaps nt compute.
template <int MODE>
__global__ void __launch_bounds__(256, 2) hgemm_kernel(
    const float* __restrict__ A,
    const __half* __restrict__ Bt,
    const float* __restrict__ bias,
    float* __restrict__ C,
    int COLS, int Mrows, int NTILES) {
    extern __shared__ char smem[];
    const uint32_t sb = smem_u32(smem);
    const int tid = threadIdx.x;
    const int m0 = blockIdx.x * 128;
    const int SM_B0 = 32768;

    auto loadB = [&](int n0, int buf) {
        uint32_t dstb = sb + SM_B0 + buf * 32768;
#pragma unroll
        for (int it = 0; it < 8; it++) {
            int u = tid + it * 256;          // 0..2047
            int row = u >> 4, kb = u & 15;
            uint32_t off = row * 256 + ((uint32_t)(kb ^ (row & 7)) << 4);
            const char* gh = (const char*)(Bt + (size_t)(n0 + row) * 128) + kb * 16;
            CP_ASYNC16(dstb + off, gh);
        }
        CP_COMMIT();
    };
    loadB(0, 0);

    // A tile: 128 rows x 128 cols fp16 (256B/row), swizzled, manual stores
#pragma unroll
    for (int it = 0; it < 8; it++) {
        int u = tid + it * 256;              // 0..2047
        int row = u >> 4, kb = u & 15;
        int gr = m0 + row;
        uint32_t off = row * 256 + ((uint32_t)(kb ^ (row & 7)) << 4);
        if (MODE == 1) {
            float4 v0 = make_float4(0.f, 0.f, 0.f, 0.f), v1 = v0;
            if (gr < Mrows) {
                const float* p = A + (size_t)gr * 128 + kb * 8;
                v0 = *(const float4*)p;
                v1 = *(const float4*)(p + 4);
            }
            uint32_t h0 = packh2(__float2half_rn(v0.x), __float2half_rn(v0.y));
            uint32_t h1 = packh2(__float2half_rn(v0.z), __float2half_rn(v0.w));
            uint32_t h2 = packh2(__float2half_rn(v1.x), __float2half_rn(v1.y));
            uint32_t h3 = packh2(__float2half_rn(v1.z), __float2half_rn(v1.w));
            *(uint4*)(smem + off) = make_uint4(h0, h1, h2, h3);
        } else {
            // A = updh0 + updh1 (padded arrays; no guard)
            const uint4 a0 = *(const uint4*)((const char*)(g_updh0 + (size_t)gr * 128) + kb * 16);
            const uint4 a1 = *(const uint4*)((const char*)(g_updh1 + (size_t)gr * 128) + kb * 16);
            *(uint4*)(smem + off) = make_uint4(addh2(a0.x, a1.x), addh2(a0.y, a1.y),
                                               addh2(a0.z, a1.z), addh2(a0.w, a1.w));
        }
    }
    if (NTILES > 1) loadB(128, 1);

    // 8 warps -> 4m x 2n grid of 32m x 64n warp tiles
    const int wid = tid >> 5, lane = tid & 31;
    const int wm = wid & 3, wn = wid >> 2;
    const uint32_t x7 = lane & 7;
    const uint32_t aRow = wm * 32 + (lane & 15);
    const uint32_t akoff = lane >> 4;
    const uint32_t bRow = wn * 64 + (lane & 7) + ((lane >> 4) << 3);
    const uint32_t bkoff = (lane >> 3) & 1;
    const uint32_t ah_base = sb + aRow * 256;
    const int g = lane >> 2, tg = lane & 3;

    for (int nt = 0; nt < NTILES; nt++) {
        if (nt + 1 < NTILES) CP_WAIT(1);
        else CP_WAIT(0);
        __syncthreads();

        const uint32_t bh_base = sb + SM_B0 + (nt & 1) * 32768 + bRow * 256;
        float acc[2][8][4] = {};
#pragma unroll
        for (int kc = 0; kc < 8; kc++) {
            const uint32_t kxa = (((2 * kc + akoff) ^ x7) << 4);
            const uint32_t kxb = (((2 * kc + bkoff) ^ x7) << 4);
            uint32_t AH[2][4], BH[4][4];
#pragma unroll
            for (int ma = 0; ma < 2; ma++) LDSM4(AH[ma], ah_base + ma * 4096 + kxa);
#pragma unroll
            for (int nb = 0; nb < 4; nb++) LDSM4(BH[nb], bh_base + nb * 4096 + kxb);
#pragma unroll
            for (int ma = 0; ma < 2; ma++)
#pragma unroll
                for (int nb = 0; nb < 4; nb++) {
                    MMAH(acc[ma][nb * 2 + 0], AH[ma], BH[nb][0], BH[nb][1]);
                    MMAH(acc[ma][nb * 2 + 1], AH[ma], BH[nb][2], BH[nb][3]);
                }
        }

        __syncthreads();
        if (nt + 2 < NTILES) loadB((nt + 2) * 128, nt & 1);

        // ---- epilogue ----
        if (MODE == 0) {
#pragma unroll
            for (int ma = 0; ma < 2; ma++) {
                int row = m0 + wm * 32 + ma * 16 + g;
#pragma unroll
                for (int x = 0; x < 8; x++) {
                    int col = nt * 128 + wn * 64 + x * 8 + tg * 2;
                    float2 bb = *(const float2*)(bias + col);
                    float* c = acc[ma][x];
                    if (row < Mrows)
                        *(float2*)(C + (size_t)row * COLS + col) =
                            make_float2(c[0] + bb.x, c[1] + bb.y);
                    if (row + 8 < Mrows)
                        *(float2*)(C + (size_t)(row + 8) * COLS + col) =
                            make_float2(c[2] + bb.x, c[3] + bb.y);
                }
            }
        } else {
            int r = nt / 3, t = nt - r * 3;
            __half* hout = (t == 0 ? g_K : t == 1 ? g_Q : g_V) + (size_t)r * N_NODES * 128;
#pragma unroll
            for (int ma = 0; ma < 2; ma++) {
                int row = m0 + wm * 32 + ma * 16 + g;
#pragma unroll
                for (int x = 0; x < 8; x++) {
                    int j = wn * 64 + x * 8 + tg * 2;
                    float2 bb = *(const float2*)(bias + nt * 128 + j);
                    float* c = acc[ma][x];
                    if (row < Mrows)
                        *(__half2*)(hout + (size_t)row * 128 + j) =
                            __float22half2_rn(make_float2(c[0] + bb.x, c[1] + bb.y));
                    if (row + 8 < Mrows)
                        *(__half2*)(hout + (size_t)(row + 8) * 128 + j) =
                            __float22half2_rn(make_float2(c[2] + bb.x, c[3] + bb.y));
                }
            }
        }
    }
}

// ---------------- gather: independent warp per (node, rel); fp16 partial write ----------------
__global__ void __launch_bounds__(256) gather_kernel() {
    int wid = threadIdx.x >> 5, lane = threadIdx.x & 31;
    int node = blockIdx.x * 8 + wid;
    if (node >= N_NODES) return;
    int rel = blockIdx.y;
    int bucket = rel * N_NODES + node;
    int o0 = g_off[bucket], o1 = g_off[bucket + 1];
    __half* updh = rel ? g_updh1 : g_updh0;
    float2* outp = (float2*)(updh + (size_t)node * 128);

    if (o0 == o1) {
        outp[lane] = make_float2(0.f, 0.f);
        return;
    }
    const size_t rbase = (size_t)rel * N_NODES * 128;
    float2 qraw = ((const float2*)(g_Q + rbase + (size_t)node * 128))[lane];
    __half2 q0 = *reinterpret_cast<__half2*>(&qraw.x);
    __half2 q1 = *reinterpret_cast<__half2*>(&qraw.y);
    float2 fq0 = __half22float2(q0), fq1 = __half22float2(q1);

    float s = 0.f;
    float4 acc = make_float4(0.f, 0.f, 0.f, 0.f);
    int sn = g_esrc[o0];
    for (int i = o0; i < o1; i++) {
        int sn_next = (i + 1 < o1) ? g_esrc[i + 1] : 0;   // prefetch next index
        float2 kraw = ((const float2*)(g_K + rbase + (size_t)sn * 128))[lane];
        float2 vraw = ((const float2*)(g_V + rbase + (size_t)sn * 128))[lane];
        __half2 a0 = *reinterpret_cast<__half2*>(&kraw.x);
        __half2 a1 = *reinterpret_cast<__half2*>(&kraw.y);
        float2 fa0 = __half22float2(a0), fa1 = __half22float2(a1);
        float p = fa0.x * fq0.x + fa0.y * fq0.y + fa1.x * fq1.x + fa1.y * fq1.y;
        // reduce within 16-lane halves (head0: lanes 0-15, head1: 16-31)
        p += __shfl_xor_sync(0xffffffffu, p, 1);
        p += __shfl_xor_sync(0xffffffffu, p, 2);
        p += __shfl_xor_sync(0xffffffffu, p, 4);
        p += __shfl_xor_sync(0xffffffffu, p, 8);
        float el = __expf(p);
        s += el;
        __half2 v0 = *reinterpret_cast<__half2*>(&vraw.x);
        __half2 v1 = *reinterpret_cast<__half2*>(&vraw.y);
        float2 f0 = __half22float2(v0), f1 = __half22float2(v1);
        acc.x += f0.x * el;
        acc.y += f0.y * el;
        acc.z += f1.x * el;
        acc.w += f1.y * el;
        sn = sn_next;
    }
    float inv = 1.f / s;
    __half2 h0 = __float22half2_rn(make_float2(acc.x * inv, acc.y * inv));
    __half2 h1 = __float22half2_rn(make_float2(acc.z * inv, acc.w * inv));
    float2 packed;
    *reinterpret_cast<__half2*>(&packed.x) = h0;
    *reinterpret_cast<__half2*>(&packed.y) = h1;
    outp[lane] = packed;
}

// ---------------- launch ----------------
extern "C" void kernel_launch(void* const* d_in, const int* in_sizes, int n_in,
                              void* d_out, int out_size) {
    const float* feat = (const float*)d_in[0];
    const int* src0 = (const int*)d_in[1];
    const int* dst0 = (const int*)d_in[2];
    const int* src1 = (const int*)d_in[3];
    const int* dst1 = (const int*)d_in[4];
    const float* Wk = (const float*)d_in[5];
    const float* bk = (const float*)d_in[6];
    const float* Wq = (const float*)d_in[7];
    const float* bq = (const float*)d_in[8];
    const float* Wv = (const float*)d_in[9];
    const float* bv = (const float*)d_in[10];
    const float* Wo = (const float*)d_in[11];
    const float* bo = (const float*)d_in[12];
    const float* We0 = (const float*)d_in[13];
    const float* be0 = (const float*)d_in[14];
    const float* We1 = (const float*)d_in[15];
    const float* be1 = (const float*)d_in[16];
    float* out = (float*)d_out;

    void *pbc, *pWC, *pWo;
    cudaGetSymbolAddress(&pbc, g_bc);
    cudaGetSymbolAddress(&pWC, g_WCt);
    cudaGetSymbolAddress(&pWo, g_Wot);

    cudaFuncSetAttribute(hgemm_kernel<1>, cudaFuncAttributeMaxDynamicSharedMemorySize, 98304);
    cudaFuncSetAttribute(hgemm_kernel<0>, cudaFuncAttributeMaxDynamicSharedMemorySize, 98304);

    // CSR build
    zero_cnt_kernel<<<(NBUCK + 255) / 256, 256>>>();
    hist_kernel<<<dim3((N_EDGES + 255) / 256, 2), 256>>>(dst0, dst1);
    scan1_kernel<<<SCAN_NB, 256>>>();
    scan2_kernel<<<1, 256>>>();
    scan3_kernel<<<SCAN_NB, 256>>>();
    scatter_kernel<<<dim3((N_EDGES + 255) / 256, 2), 256>>>(src0, dst0, src1, dst1);

    // weights
    prep_kernel<<<KQV_COLS, 128>>>(Wk, bk, Wq, bq, Wv, bv, We0, be0, We1, be1);
    prep_wo_kernel<<<128, 128>>>(Wo);

    const int Mtiles = (N_NODES + 127) / 128;  // 1563

    // K/Q/V = feat @ WC + bc   (single-pass fp16, double-buffered B)
    hgemm_kernel<1><<<Mtiles, 256, 98304>>>(
        feat, (const __half*)pWC, (const float*)pbc, nullptr, KQV_COLS, N_NODES, 6);

    // per-destination softmax + message aggregation (independent warps) -> fp16 partials
    gather_kernel<<<dim3((N_NODES + 7) / 8, 2), 256>>>();

    // out = (updh0 + updh1) @ Wo + bo   (fp16 single-pass)
    hgemm_kernel<0><<<Mtiles, 256, 98304>>>(
        nullptr, (const __half*)pWo, bo, out, DIM, N_NODES, 1);
}